// round 14
// baseline (speedup 1.0000x reference)
#include <cuda_runtime.h>
#include <cstdint>

typedef unsigned long long ull;

#define FHW 32
#define NA 9
#define NBOX (FHW*FHW*NA)   // 9216
#define NW 144              // mask words per sorted row (9216/64)
#define CIN 256
#define IMGF 512.0f
#define NBLK 144            // rank+mask grid (all resident on 148 SMs)

// ---------------- scratch ----------------
__device__ float  g_h[1024*512];                 // h[pos][och], 2 MB
__device__ float4 g_boxes[NBOX];
__device__ float  g_scores[NBOX];
__device__ ull    g_vkey[NBOX];                  // compacted valid keys
__device__ int    g_vn[NBOX];                    // compacted valid original idx
__device__ int    g_sidx[NBOX];
__device__ float4 g_sboxes[NBOX];
__device__ ull    g_maskT[(size_t)NW*NBOX];      // TRANSPOSED: [word][row]
__device__ int    g_keep[NBOX];
__device__ int    g_M;
__device__ unsigned g_bar_cnt = 0;               // wraps to 0 each use (replay-safe)
__device__ unsigned g_bar_gen = 0;               // monotonic; compared relatively

__constant__ float c_aw[9] = {45.254833995939045f, 32.0f, 22.627416997969522f,
                              90.50966799187809f,  64.0f, 45.254833995939045f,
                              181.01933598375618f, 128.0f, 90.50966799187809f};
__constant__ float c_ah[9] = {22.627416997969522f, 32.0f, 45.254833995939045f,
                              45.254833995939045f, 64.0f, 90.50966799187809f,
                              90.50966799187809f,  128.0f, 181.01933598375618f};

// packed dual-fp32 FMA (Blackwell): acc = a*b + acc, per 32-bit lane
#define FMA2(acc, a, b) asm("fma.rn.f32x2 %0, %1, %2, %0;" : "+l"(acc) : "l"(a), "l"(b))

// ---------------- kernel 1: 3x3 conv 256->512 + bias + relu (f32x2) ----------------
__global__ __launch_bounds__(128) void k_conv(const float* __restrict__ x,
                                              const float* __restrict__ w,
                                              const float* __restrict__ b)
{
    __shared__ ull   xs2[16][10][10];     // [c][col][row], value packed {x,x}
    __shared__ float ws[4896];            // [(c*9+tap)*34 + och], stride 34

    const int tid = threadIdx.x;
    const int x0 = (blockIdx.x & 3) * 8, y0 = (blockIdx.x >> 2) * 8;
    const int ob = blockIdx.y * 32;
    const int pt = tid & 31, ot = tid >> 5;
    const int cg = pt & 3, pr = pt >> 2;
    const int cg2 = cg * 2, ot8 = ot * 8;

    if (blockIdx.x == 0 && blockIdx.y == 0 && tid == 0) g_M = 0;

    ull acc2[4][2];
    #pragma unroll
    for (int o = 0; o < 4; o++)
        #pragma unroll
        for (int i = 0; i < 2; i++) acc2[o][i] = 0ull;

    for (int c0 = 0; c0 < CIN; c0 += 16) {
        __syncthreads();
        for (int t = tid; t < 16*10*10; t += 128) {
            int c = t / 100, r2 = t - c*100, col = r2 / 10, row = r2 - col*10;
            int gx = x0 + col - 1, gy = y0 + row - 1;
            float v = 0.0f;
            if ((unsigned)gx < 32u && (unsigned)gy < 32u)
                v = x[(c0 + c) * 1024 + gy * 32 + gx];
            unsigned xb = __float_as_uint(v);
            ull pv; asm("mov.b64 %0, {%1, %1};" : "=l"(pv) : "r"(xb));
            xs2[c][col][row] = pv;
        }
        {
            int o = 0, rr = tid;
            #pragma unroll 4
            for (int k = 0; k < 36; k++) {
                ws[rr * 34 + o] = w[(size_t)(ob + o) * 2304 + c0 * 9 + rr];
                rr += 128; if (rr >= 144) { rr -= 144; o++; }
            }
        }
        __syncthreads();

        for (int c = 0; c < 16; c++) {
            #pragma unroll
            for (int dy = 0; dy < 3; dy++) {
                ull xv[4];
                #pragma unroll
                for (int q = 0; q < 4; q++) xv[q] = xs2[c][cg2 + q][pr + dy];
                #pragma unroll
                for (int dx = 0; dx < 3; dx++) {
                    const ull* wp = (const ull*)&ws[(c*9 + dy*3 + dx) * 34 + ot8];
                    ull w0 = wp[0], w1 = wp[1], w2v = wp[2], w3v = wp[3];
                    #pragma unroll
                    for (int i = 0; i < 2; i++) {
                        ull xp = xv[i + dx];
                        FMA2(acc2[0][i], w0,  xp);
                        FMA2(acc2[1][i], w1,  xp);
                        FMA2(acc2[2][i], w2v, xp);
                        FMA2(acc2[3][i], w3v, xp);
                    }
                }
            }
        }
    }

    float bias[8];
    #pragma unroll
    for (int o = 0; o < 8; o++) bias[o] = b[ob + ot8 + o];

    const int px = x0 + cg2, py = y0 + pr;
    #pragma unroll
    for (int i = 0; i < 2; i++) {
        int p = py * 32 + px + i;
        float r[8];
        #pragma unroll
        for (int op = 0; op < 4; op++) {
            ull v = acc2[op][i];
            r[2*op]   = __uint_as_float((unsigned)v);
            r[2*op+1] = __uint_as_float((unsigned)(v >> 32));
        }
        float4 v0, v1;
        v0.x = fmaxf(r[0] + bias[0], 0.0f); v0.y = fmaxf(r[1] + bias[1], 0.0f);
        v0.z = fmaxf(r[2] + bias[2], 0.0f); v0.w = fmaxf(r[3] + bias[3], 0.0f);
        v1.x = fmaxf(r[4] + bias[4], 0.0f); v1.y = fmaxf(r[5] + bias[5], 0.0f);
        v1.z = fmaxf(r[6] + bias[6], 0.0f); v1.w = fmaxf(r[7] + bias[7], 0.0f);
        float* hp = &g_h[(size_t)p * 512 + ob + ot8];
        *(float4*)hp       = v0;
        *(float4*)(hp + 4) = v1;
    }
}

// ---------------- kernel 2: heads, 4 positions/block (256 blocks), valid compaction ----
__global__ __launch_bounds__(128) void k_heads(const float* __restrict__ w2, const float* __restrict__ b2,
                                               const float* __restrict__ w3, const float* __restrict__ b3)
{
    __shared__ __align__(16) float hs[4][512];
    __shared__ float outv[45][4];
    const int pb = blockIdx.x * 4;
    const int tid = threadIdx.x;
    if (tid < 36) g_keep[pb * 9 + tid] = 0;      // reset keep flags for replay

    const float4* src = (const float4*)(g_h + (size_t)pb * 512);
    float4* dst = (float4*)&hs[0][0];
    #pragma unroll
    for (int t = tid; t < 512; t += 128) dst[t] = src[t];
    __syncthreads();

    const int wrp = tid >> 5, lane = tid & 31;
    for (int o = wrp; o < 45; o += 4) {
        const float* wr; float bb;
        if (o < 9) { wr = w2 + o * 512;       bb = b2[o];     }
        else       { wr = w3 + (o - 9) * 512; bb = b3[o - 9]; }
        float acc[4];
        #pragma unroll
        for (int p = 0; p < 4; p++) acc[p] = 0.0f;
        #pragma unroll 4
        for (int ci = 0; ci < 16; ci++) {
            int c = ci * 32 + lane;
            float wv = wr[c];
            #pragma unroll
            for (int p = 0; p < 4; p++) acc[p] += hs[p][c] * wv;
        }
        #pragma unroll
        for (int p = 0; p < 4; p++) {
            float s = acc[p];
            #pragma unroll
            for (int off = 16; off; off >>= 1) s += __shfl_down_sync(0xffffffffu, s, off);
            if (lane == 0) outv[o][p] = s + bb;
        }
    }
    __syncthreads();

    if (tid < 36) {
        const int pl = tid / 9, a = tid - pl * 9;
        const int p = pb + pl;
        const int y = p >> 5, xx = p & 31;
        float score = 1.0f / (1.0f + expf(-outv[a][pl]));
        float t0 = outv[9 + a*4 + 0][pl], t1 = outv[9 + a*4 + 1][pl];
        float t2 = outv[9 + a*4 + 2][pl], t3 = outv[9 + a*4 + 3][pl];
        float aw = c_aw[a], ah = c_ah[a];
        float acx = (xx + 0.5f) * 16.0f, acy = (y + 0.5f) * 16.0f;
        float cx = acx + t0 * aw, cy = acy + t1 * ah;
        float bw = aw * expf(t2), bh = ah * expf(t3);
        float x1 = cx - bw * 0.5f, y1 = cy - bh * 0.5f;
        float x2 = cx + bw * 0.5f, y2 = cy + bh * 0.5f;
        x1 = fminf(fmaxf(x1, 0.0f), IMGF); y1 = fminf(fmaxf(y1, 0.0f), IMGF);
        x2 = fminf(fmaxf(x2, 0.0f), IMGF); y2 = fminf(fmaxf(y2, 0.0f), IMGF);
        bool valid = (x2 - x1 >= 0.001f) && (y2 - y1 >= 0.001f) && (score >= 0.5f);
        int n = p * 9 + a;
        g_scores[n] = score;
        g_boxes[n] = make_float4(x1, y1, x2, y2);
        if (valid) {
            // compacted valid list; slot order nondeterministic, ranks deterministic
            int slot = atomicAdd(&g_M, 1);
            g_vkey[slot] = ((ull)__float_as_uint(score) << 32)
                         | (ull)(0xFFFFFFFFu - (unsigned)n);
            g_vn[slot] = n;
        }
    }
}

// ---------------- grid barrier: release via atomic, wait via volatile LOAD ----------
__device__ __forceinline__ void grid_bar()
{
    __syncthreads();
    if (threadIdx.x == 0) {
        __threadfence();
        unsigned target = *(volatile unsigned*)&g_bar_gen + 1u;
        unsigned old = atomicInc(&g_bar_cnt, NBLK - 1u);   // wraps to 0 at NBLK
        if (old == NBLK - 1u) {
            __threadfence();
            atomicAdd(&g_bar_gen, 1u);
        } else {
            while ((int)(*(volatile unsigned*)&g_bar_gen - target) < 0) __nanosleep(100);
        }
    }
    __syncthreads();
}

// ---------------- kernel 3: rank (valid-only) + grid barrier + mask ----------------
__global__ __launch_bounds__(256) void k_rankmask()
{
    __shared__ union {
        struct { ull ks[1024]; } r;
        struct { float4 cb[64]; float carea[64]; } m;
    } sm;

    const int bid = blockIdx.x;
    const int tid = threadIdx.x;
    const int M = g_M;

    // ---- phase A: rank compacted valid keys (enumeration, 8 threads/key) ----
    {
        const int kl = tid >> 3, sub = tid & 7;
        for (int i0 = 0; i0 < M; i0 += NBLK * 32) {
            const int ki = i0 + bid * 32 + kl;
            const ull mykey = (ki < M) ? g_vkey[ki] : ~0ull;
            int cnt = 0;
            for (int t0 = 0; t0 < M; t0 += 1024) {
                __syncthreads();
                #pragma unroll
                for (int t = tid; t < 1024; t += 256)
                    sm.r.ks[t] = (t0 + t < M) ? g_vkey[t0 + t] : 0ull;
                __syncthreads();
                #pragma unroll 8
                for (int t = 0; t < 128; t++) cnt += (sm.r.ks[t * 8 + sub] > mykey) ? 1 : 0;
            }
            cnt += __shfl_down_sync(0xffffffffu, cnt, 4, 8);
            cnt += __shfl_down_sync(0xffffffffu, cnt, 2, 8);
            cnt += __shfl_down_sync(0xffffffffu, cnt, 1, 8);
            if (sub == 0 && ki < M) {
                int n = g_vn[ki];
                g_sidx[cnt] = n;               // unique keys -> cnt is a permutation of [0,M)
                g_sboxes[cnt] = g_boxes[n];
            }
        }
    }
    grid_bar();

    // ---- phase B: suppression bitmask (work-list tiles; window-compare IOU) ----
    {
        const int ncw = (M + 63) >> 6;
        const int nrp = (M + 255) >> 8;
        for (int t = bid; t < ncw * nrp; t += NBLK) {
            const int cw = t % ncw, rp = t / ncw;
            const int r0 = rp * 256;
            if (r0 >= M || r0 >= (cw + 1) * 64) continue;

            __syncthreads();
            if (tid < 64) {
                float4 bb = g_sboxes[cw * 64 + tid];
                sm.m.cb[tid] = bb;
                sm.m.carea[tid] = (bb.z - bb.x) * (bb.w - bb.y);
            }
            __syncthreads();

            const int r = r0 + tid;
            const int d = r - cw * 64;
            if (r < M && d <= 63) {
                ull allow = ~0ull;
                if (d >= 0) allow = (d >= 63) ? 0ull : (~0ull << (d + 1));
                int rem = M - cw * 64;
                if (rem < 64) allow &= ((1ull << rem) - 1ull);

                ull word = 0ull;
                if (allow) {
                    float4 mb = g_sboxes[r];
                    float ma = (mb.z - mb.x) * (mb.w - mb.y);
                    unsigned bits[2] = {0u, 0u};
                    unsigned amb[2]  = {0u, 0u};
                    #pragma unroll
                    for (int half = 0; half < 2; half++) {
                        #pragma unroll
                        for (int jj = 0; jj < 32; jj++) {
                            int j = half * 32 + jj;
                            float4 ob = sm.m.cb[j];
                            float ix1 = fmaxf(mb.x, ob.x), iy1 = fmaxf(mb.y, ob.y);
                            float ix2 = fminf(mb.z, ob.z), iy2 = fminf(mb.w, ob.w);
                            float inter = fmaxf(ix2 - ix1, 0.0f) * fmaxf(iy2 - iy1, 0.0f);
                            float uni = ma + sm.m.carea[j] - inter;
                            bool h = inter > 0.7000004f * uni;
                            bool l = inter > 0.6999996f * uni;
                            bits[half] |= ((unsigned)h) << jj;
                            amb[half]  |= ((unsigned)(h != l)) << jj;
                        }
                    }
                    #pragma unroll
                    for (int half = 0; half < 2; half++) {
                        unsigned a = amb[half];
                        while (a) {
                            int jj = __ffs(a) - 1; a &= a - 1;
                            int j = half * 32 + jj;
                            float4 ob = sm.m.cb[j];
                            float ix1 = fmaxf(mb.x, ob.x), iy1 = fmaxf(mb.y, ob.y);
                            float ix2 = fminf(mb.z, ob.z), iy2 = fminf(mb.w, ob.w);
                            float inter = fmaxf(ix2 - ix1, 0.0f) * fmaxf(iy2 - iy1, 0.0f);
                            float uni = ma + sm.m.carea[j] - inter;
                            bool s = (inter / fmaxf(uni, 1e-9f)) > 0.7f;
                            bits[half] = (bits[half] & ~(1u << jj)) | (((unsigned)s) << jj);
                        }
                    }
                    word = (((ull)bits[1] << 32) | bits[0]) & allow;
                }
                g_maskT[(size_t)cw * NBOX + r] = word;
            }
        }
    }
}

// ---------------- kernel 4: pipelined greedy scan + output write (1 block) ----------
__global__ __launch_bounds__(256) void k_scanout(float* __restrict__ out)
{
    __shared__ int krows[NBOX];
    __shared__ ull selfw[64];
    __shared__ ull warp_or[8];
    __shared__ unsigned act_lo, act_hi;
    __shared__ ull kb_s;
    __shared__ int kc_s;
    const int tid = threadIdx.x;
    const int lane = tid & 31, wrp = tid >> 5;
    const int M = g_M;
    const int nwords = (M + 63) >> 6;
    if (tid == 0) kc_s = 0;
    if (tid < 8) warp_or[tid] = 0ull;
    __syncthreads();

    ull accR = 0ull, specR = 0ull, swR = 0ull;
    if (nwords > 0 && tid < 64)
        swR = (tid < M) ? g_maskT[(size_t)0 * NBOX + tid] : 0ull;
    ull kbPrev = 0ull;

    for (int w = 0; w < nwords; w++) {
        const int rbase = w << 6;
        const int cnt = min(64, M - rbase);
        const int kc = kc_s;

        ull accN = 0ull, specN = 0ull, swN = 0ull;
        if (w + 1 < nwords) {
            const size_t nb = (size_t)(w + 1) * NBOX;
            #pragma unroll 4
            for (int kk = tid; kk < kc; kk += 256)
                accN |= g_maskT[nb + krows[kk]];
            if (tid < 64) {
                specN = (rbase + tid < M)      ? g_maskT[nb + rbase + tid]      : 0ull;
                swN   = (rbase + 64 + tid < M) ? g_maskT[nb + rbase + 64 + tid] : 0ull;
            }
        }

        ull contrib = accR;
        if (tid < 64) {
            if ((kbPrev >> tid) & 1ull) contrib |= specR;
            selfw[tid] = swR;
        }
        if (wrp == 0) {
            unsigned bl = __ballot_sync(0xffffffffu, swR != 0ull);
            if (lane == 0) act_lo = bl;
        } else if (wrp == 1) {
            unsigned bl = __ballot_sync(0xffffffffu, swR != 0ull);
            if (lane == 0) act_hi = bl;
        }
        #pragma unroll
        for (int off = 16; off; off >>= 1)
            contrib |= __shfl_xor_sync(0xffffffffu, contrib, off);
        if (lane == 0) warp_or[wrp] = contrib;
        __syncthreads();

        if (tid == 0) {
            ull sup = warp_or[0] | warp_or[1] | warp_or[2] | warp_or[3]
                    | warp_or[4] | warp_or[5] | warp_or[6] | warp_or[7];
            const ull active = ((ull)act_hi << 32) | act_lo;
            const ull full = (cnt < 64) ? ((1ull << cnt) - 1ull) : ~0ull;
            ull act = active & ~sup & full;
            while (act) {
                int rr = __ffsll((long long)act) - 1;
                sup |= selfw[rr];
                ull above = (rr >= 63) ? 0ull : (~0ull << (rr + 1));
                act = active & ~sup & above;
            }
            kb_s = ~sup & full;
        }
        __syncthreads();

        const ull kb = kb_s;
        if (tid < cnt && ((kb >> tid) & 1ull)) {
            int pos = __popcll(kb & ((1ull << tid) - 1ull));
            krows[kc + pos] = rbase + tid;
            g_keep[g_sidx[rbase + tid]] = 1;
        }
        if (tid == 0) kc_s = kc + __popcll(kb);
        kbPrev = kb;
        accR = accN; specR = specN; swR = swN;
        __syncthreads();
    }

    // ---- output tail: 256 threads write all 9216 rows ----
    for (int n = tid; n < NBOX; n += 256) {
        float m = g_keep[n] ? 1.0f : 0.0f;
        float4 bx = g_boxes[n];
        float s = g_scores[n];
        float* o = out + (size_t)n * 5;
        o[0] = bx.x * m; o[1] = bx.y * m; o[2] = bx.z * m; o[3] = bx.w * m; o[4] = s * m;
    }
}

// ---------------- launch ----------------
extern "C" void kernel_launch(void* const* d_in, const int* in_sizes, int n_in,
                              void* d_out, int out_size)
{
    const float* fm = (const float*)d_in[0];
    const float* w1 = (const float*)d_in[1];
    const float* b1 = (const float*)d_in[2];
    const float* w2 = (const float*)d_in[3];
    const float* b2 = (const float*)d_in[4];
    const float* w3 = (const float*)d_in[5];
    const float* b3 = (const float*)d_in[6];

    k_conv    <<<dim3(16, 16), 128>>>(fm, w1, b1);
    k_heads   <<<256, 128>>>(w2, b2, w3, b3);
    k_rankmask<<<NBLK, 256>>>();
    k_scanout <<<1, 256>>>((float*)d_out);
}

// round 16
// speedup vs baseline: 1.0111x; 1.0111x over previous
#include <cuda_runtime.h>
#include <cstdint>

typedef unsigned long long ull;

#define FHW 32
#define NA 9
#define NBOX (FHW*FHW*NA)   // 9216
#define NW 144              // mask words per sorted row (9216/64)
#define CIN 256
#define IMGF 512.0f
#define NBLK 144            // rank+mask grid (all resident on 148 SMs)

// ---------------- scratch ----------------
__device__ float  g_h[1024*512];                 // h[pos][och], 2 MB
__device__ float4 g_boxes[NBOX];
__device__ float  g_scores[NBOX];
__device__ ull    g_vkey[NBOX];                  // compacted valid keys
__device__ int    g_vn[NBOX];                    // compacted valid original idx
__device__ int    g_sidx[NBOX];
__device__ float4 g_sboxes[NBOX];
__device__ ull    g_maskT[(size_t)NW*NBOX];      // TRANSPOSED: [word][row]
__device__ ull    g_nzw[NBOX][3];                // per sorted row: bitmap of nonzero FUTURE words
__device__ int    g_keep[NBOX];
__device__ int    g_M;
__device__ unsigned g_bar_cnt = 0;               // wraps to 0 each use (replay-safe)
__device__ unsigned g_bar_gen = 0;               // monotonic; compared relatively

__constant__ float c_aw[9] = {45.254833995939045f, 32.0f, 22.627416997969522f,
                              90.50966799187809f,  64.0f, 45.254833995939045f,
                              181.01933598375618f, 128.0f, 90.50966799187809f};
__constant__ float c_ah[9] = {22.627416997969522f, 32.0f, 45.254833995939045f,
                              45.254833995939045f, 64.0f, 90.50966799187809f,
                              90.50966799187809f,  128.0f, 181.01933598375618f};

// packed dual-fp32 FMA (Blackwell): acc = a*b + acc, per 32-bit lane
#define FMA2(acc, a, b) asm("fma.rn.f32x2 %0, %1, %2, %0;" : "+l"(acc) : "l"(a), "l"(b))

// ---------------- kernel 1: 3x3 conv 256->512 + bias + relu (f32x2) ----------------
__global__ __launch_bounds__(128) void k_conv(const float* __restrict__ x,
                                              const float* __restrict__ w,
                                              const float* __restrict__ b)
{
    __shared__ ull   xs2[16][10][10];     // [c][col][row], value packed {x,x}
    __shared__ float ws[4896];            // [(c*9+tap)*34 + och], stride 34

    const int tid = threadIdx.x;
    const int x0 = (blockIdx.x & 3) * 8, y0 = (blockIdx.x >> 2) * 8;
    const int ob = blockIdx.y * 32;
    const int pt = tid & 31, ot = tid >> 5;
    const int cg = pt & 3, pr = pt >> 2;
    const int cg2 = cg * 2, ot8 = ot * 8;

    if (blockIdx.x == 0 && blockIdx.y == 0 && tid == 0) g_M = 0;

    ull acc2[4][2];
    #pragma unroll
    for (int o = 0; o < 4; o++)
        #pragma unroll
        for (int i = 0; i < 2; i++) acc2[o][i] = 0ull;

    for (int c0 = 0; c0 < CIN; c0 += 16) {
        __syncthreads();
        for (int t = tid; t < 16*10*10; t += 128) {
            int c = t / 100, r2 = t - c*100, col = r2 / 10, row = r2 - col*10;
            int gx = x0 + col - 1, gy = y0 + row - 1;
            float v = 0.0f;
            if ((unsigned)gx < 32u && (unsigned)gy < 32u)
                v = x[(c0 + c) * 1024 + gy * 32 + gx];
            unsigned xb = __float_as_uint(v);
            ull pv; asm("mov.b64 %0, {%1, %1};" : "=l"(pv) : "r"(xb));
            xs2[c][col][row] = pv;
        }
        {
            int o = 0, rr = tid;
            #pragma unroll 4
            for (int k = 0; k < 36; k++) {
                ws[rr * 34 + o] = w[(size_t)(ob + o) * 2304 + c0 * 9 + rr];
                rr += 128; if (rr >= 144) { rr -= 144; o++; }
            }
        }
        __syncthreads();

        for (int c = 0; c < 16; c++) {
            #pragma unroll
            for (int dy = 0; dy < 3; dy++) {
                ull xv[4];
                #pragma unroll
                for (int q = 0; q < 4; q++) xv[q] = xs2[c][cg2 + q][pr + dy];
                #pragma unroll
                for (int dx = 0; dx < 3; dx++) {
                    const ull* wp = (const ull*)&ws[(c*9 + dy*3 + dx) * 34 + ot8];
                    ull w0 = wp[0], w1 = wp[1], w2v = wp[2], w3v = wp[3];
                    #pragma unroll
                    for (int i = 0; i < 2; i++) {
                        ull xp = xv[i + dx];
                        FMA2(acc2[0][i], w0,  xp);
                        FMA2(acc2[1][i], w1,  xp);
                        FMA2(acc2[2][i], w2v, xp);
                        FMA2(acc2[3][i], w3v, xp);
                    }
                }
            }
        }
    }

    float bias[8];
    #pragma unroll
    for (int o = 0; o < 8; o++) bias[o] = b[ob + ot8 + o];

    const int px = x0 + cg2, py = y0 + pr;
    #pragma unroll
    for (int i = 0; i < 2; i++) {
        int p = py * 32 + px + i;
        float r[8];
        #pragma unroll
        for (int op = 0; op < 4; op++) {
            ull v = acc2[op][i];
            r[2*op]   = __uint_as_float((unsigned)v);
            r[2*op+1] = __uint_as_float((unsigned)(v >> 32));
        }
        float4 v0, v1;
        v0.x = fmaxf(r[0] + bias[0], 0.0f); v0.y = fmaxf(r[1] + bias[1], 0.0f);
        v0.z = fmaxf(r[2] + bias[2], 0.0f); v0.w = fmaxf(r[3] + bias[3], 0.0f);
        v1.x = fmaxf(r[4] + bias[4], 0.0f); v1.y = fmaxf(r[5] + bias[5], 0.0f);
        v1.z = fmaxf(r[6] + bias[6], 0.0f); v1.w = fmaxf(r[7] + bias[7], 0.0f);
        float* hp = &g_h[(size_t)p * 512 + ob + ot8];
        *(float4*)hp       = v0;
        *(float4*)(hp + 4) = v1;
    }
}

// ---------------- kernel 2: heads, 4 positions/block, valid compaction + nzw init ----
__global__ __launch_bounds__(128) void k_heads(const float* __restrict__ w2, const float* __restrict__ b2,
                                               const float* __restrict__ w3, const float* __restrict__ b3)
{
    __shared__ __align__(16) float hs[4][512];
    __shared__ float outv[45][4];
    const int pb = blockIdx.x * 4;
    const int tid = threadIdx.x;
    if (tid < 36) g_keep[pb * 9 + tid] = 0;      // reset keep flags for replay
    if (tid < 108) ((ull*)g_nzw)[blockIdx.x * 108 + tid] = 0ull;  // reset bitmaps

    const float4* src = (const float4*)(g_h + (size_t)pb * 512);
    float4* dst = (float4*)&hs[0][0];
    #pragma unroll
    for (int t = tid; t < 512; t += 128) dst[t] = src[t];
    __syncthreads();

    const int wrp = tid >> 5, lane = tid & 31;
    for (int o = wrp; o < 45; o += 4) {
        const float* wr; float bb;
        if (o < 9) { wr = w2 + o * 512;       bb = b2[o];     }
        else       { wr = w3 + (o - 9) * 512; bb = b3[o - 9]; }
        float acc[4];
        #pragma unroll
        for (int p = 0; p < 4; p++) acc[p] = 0.0f;
        #pragma unroll 4
        for (int ci = 0; ci < 16; ci++) {
            int c = ci * 32 + lane;
            float wv = wr[c];
            #pragma unroll
            for (int p = 0; p < 4; p++) acc[p] += hs[p][c] * wv;
        }
        #pragma unroll
        for (int p = 0; p < 4; p++) {
            float s = acc[p];
            #pragma unroll
            for (int off = 16; off; off >>= 1) s += __shfl_down_sync(0xffffffffu, s, off);
            if (lane == 0) outv[o][p] = s + bb;
        }
    }
    __syncthreads();

    if (tid < 36) {
        const int pl = tid / 9, a = tid - pl * 9;
        const int p = pb + pl;
        const int y = p >> 5, xx = p & 31;
        float score = 1.0f / (1.0f + expf(-outv[a][pl]));
        float t0 = outv[9 + a*4 + 0][pl], t1 = outv[9 + a*4 + 1][pl];
        float t2 = outv[9 + a*4 + 2][pl], t3 = outv[9 + a*4 + 3][pl];
        float aw = c_aw[a], ah = c_ah[a];
        float acx = (xx + 0.5f) * 16.0f, acy = (y + 0.5f) * 16.0f;
        float cx = acx + t0 * aw, cy = acy + t1 * ah;
        float bw = aw * expf(t2), bh = ah * expf(t3);
        float x1 = cx - bw * 0.5f, y1 = cy - bh * 0.5f;
        float x2 = cx + bw * 0.5f, y2 = cy + bh * 0.5f;
        x1 = fminf(fmaxf(x1, 0.0f), IMGF); y1 = fminf(fmaxf(y1, 0.0f), IMGF);
        x2 = fminf(fmaxf(x2, 0.0f), IMGF); y2 = fminf(fmaxf(y2, 0.0f), IMGF);
        bool valid = (x2 - x1 >= 0.001f) && (y2 - y1 >= 0.001f) && (score >= 0.5f);
        int n = p * 9 + a;
        g_scores[n] = score;
        g_boxes[n] = make_float4(x1, y1, x2, y2);
        if (valid) {
            // compacted valid list; slot order nondeterministic, ranks deterministic
            int slot = atomicAdd(&g_M, 1);
            g_vkey[slot] = ((ull)__float_as_uint(score) << 32)
                         | (ull)(0xFFFFFFFFu - (unsigned)n);
            g_vn[slot] = n;
        }
    }
}

// ---------------- grid barrier: release via atomic, wait via volatile LOAD ----------
__device__ __forceinline__ void grid_bar()
{
    __syncthreads();
    if (threadIdx.x == 0) {
        __threadfence();
        unsigned target = *(volatile unsigned*)&g_bar_gen + 1u;
        unsigned old = atomicInc(&g_bar_cnt, NBLK - 1u);   // wraps to 0 at NBLK
        if (old == NBLK - 1u) {
            __threadfence();
            atomicAdd(&g_bar_gen, 1u);
        } else {
            while ((int)(*(volatile unsigned*)&g_bar_gen - target) < 0) __nanosleep(100);
        }
    }
    __syncthreads();
}

// ---------------- kernel 3: rank (valid-only) + grid barrier + mask + nzw bitmap ----
__global__ __launch_bounds__(256) void k_rankmask()
{
    __shared__ union {
        struct { ull ks[1024]; } r;
        struct { float4 cb[64]; float carea[64]; } m;
    } sm;

    const int bid = blockIdx.x;
    const int tid = threadIdx.x;
    const int M = g_M;

    // ---- phase A: rank compacted valid keys (enumeration, 8 threads/key) ----
    {
        const int kl = tid >> 3, sub = tid & 7;
        for (int i0 = 0; i0 < M; i0 += NBLK * 32) {
            const int ki = i0 + bid * 32 + kl;
            const ull mykey = (ki < M) ? g_vkey[ki] : ~0ull;
            int cnt = 0;
            for (int t0 = 0; t0 < M; t0 += 1024) {
                __syncthreads();
                #pragma unroll
                for (int t = tid; t < 1024; t += 256)
                    sm.r.ks[t] = (t0 + t < M) ? g_vkey[t0 + t] : 0ull;
                __syncthreads();
                #pragma unroll 8
                for (int t = 0; t < 128; t++) cnt += (sm.r.ks[t * 8 + sub] > mykey) ? 1 : 0;
            }
            cnt += __shfl_down_sync(0xffffffffu, cnt, 4, 8);
            cnt += __shfl_down_sync(0xffffffffu, cnt, 2, 8);
            cnt += __shfl_down_sync(0xffffffffu, cnt, 1, 8);
            if (sub == 0 && ki < M) {
                int n = g_vn[ki];
                g_sidx[cnt] = n;               // unique keys -> cnt is a permutation of [0,M)
                g_sboxes[cnt] = g_boxes[n];
            }
        }
    }
    grid_bar();

    // ---- phase B: suppression bitmask (window-compare IOU) + nonzero-word bitmap ----
    {
        const int ncw = (M + 63) >> 6;
        const int nrp = (M + 255) >> 8;
        for (int t = bid; t < ncw * nrp; t += NBLK) {
            const int cw = t % ncw, rp = t / ncw;
            const int r0 = rp * 256;
            if (r0 >= M || r0 >= (cw + 1) * 64) continue;

            __syncthreads();
            if (tid < 64) {
                float4 bb = g_sboxes[cw * 64 + tid];
                sm.m.cb[tid] = bb;
                sm.m.carea[tid] = (bb.z - bb.x) * (bb.w - bb.y);
            }
            __syncthreads();

            const int r = r0 + tid;
            const int d = r - cw * 64;
            if (r < M && d <= 63) {
                ull allow = ~0ull;
                if (d >= 0) allow = (d >= 63) ? 0ull : (~0ull << (d + 1));
                int rem = M - cw * 64;
                if (rem < 64) allow &= ((1ull << rem) - 1ull);

                ull word = 0ull;
                if (allow) {
                    float4 mb = g_sboxes[r];
                    float ma = (mb.z - mb.x) * (mb.w - mb.y);
                    unsigned bits[2] = {0u, 0u};
                    unsigned amb[2]  = {0u, 0u};
                    #pragma unroll
                    for (int half = 0; half < 2; half++) {
                        #pragma unroll
                        for (int jj = 0; jj < 32; jj++) {
                            int j = half * 32 + jj;
                            float4 ob = sm.m.cb[j];
                            float ix1 = fmaxf(mb.x, ob.x), iy1 = fmaxf(mb.y, ob.y);
                            float ix2 = fminf(mb.z, ob.z), iy2 = fminf(mb.w, ob.w);
                            float inter = fmaxf(ix2 - ix1, 0.0f) * fmaxf(iy2 - iy1, 0.0f);
                            float uni = ma + sm.m.carea[j] - inter;
                            bool h = inter > 0.7000004f * uni;
                            bool l = inter > 0.6999996f * uni;
                            bits[half] |= ((unsigned)h) << jj;
                            amb[half]  |= ((unsigned)(h != l)) << jj;
                        }
                    }
                    #pragma unroll
                    for (int half = 0; half < 2; half++) {
                        unsigned a = amb[half];
                        while (a) {
                            int jj = __ffs(a) - 1; a &= a - 1;
                            int j = half * 32 + jj;
                            float4 ob = sm.m.cb[j];
                            float ix1 = fmaxf(mb.x, ob.x), iy1 = fmaxf(mb.y, ob.y);
                            float ix2 = fminf(mb.z, ob.z), iy2 = fminf(mb.w, ob.w);
                            float inter = fmaxf(ix2 - ix1, 0.0f) * fmaxf(iy2 - iy1, 0.0f);
                            float uni = ma + sm.m.carea[j] - inter;
                            bool s = (inter / fmaxf(uni, 1e-9f)) > 0.7f;
                            bits[half] = (bits[half] & ~(1u << jj)) | (((unsigned)s) << jj);
                        }
                    }
                    word = (((ull)bits[1] << 32) | bits[0]) & allow;
                }
                g_maskT[(size_t)cw * NBOX + r] = word;
                // sparse index: row r suppresses into FUTURE word cw
                if (word != 0ull && cw > (r >> 6))
                    atomicOr(&g_nzw[r][cw >> 6], 1ull << (cw & 63));
            }
        }
    }
}

// ---------------- kernel 4: sparse eager greedy scan + output (1 block) -------------
// remv[144] lives in smem. Kept rows OR only their (few) nonzero future mask
// words into remv (per-row bitmap g_nzw). Phase A needs ZERO gmem loads;
// diagonal + bitmaps + up-to-4 mask words prefetched/speculated a word ahead.
__global__ __launch_bounds__(256) void k_scanout(float* __restrict__ out)
{
    __shared__ ull remv[NW];
    __shared__ ull selfw[64];
    __shared__ unsigned act_lo, act_hi;
    __shared__ ull kb_s;
    const int tid = threadIdx.x;
    const int lane = tid & 31, wrp = tid >> 5;
    const int M = g_M;
    const int nwords = (M + 63) >> 6;
    for (int t = tid; t < NW; t += 256) remv[t] = 0ull;

    // prologue: word 0's diagonal + bitmaps
    ull swR = 0ull, bmR0 = 0ull, bmR1 = 0ull, bmR2 = 0ull;
    if (nwords > 0 && tid < 64 && tid < M) {
        swR = g_maskT[tid];
        const ull* bp = g_nzw[tid];
        bmR0 = bp[0]; bmR1 = bp[1]; bmR2 = bp[2];
    }
    __syncthreads();

    for (int w = 0; w < nwords; w++) {
        const int rbase = w << 6;
        const int cnt = min(64, M - rbase);

        // prefetch next word's diagonal + bitmaps
        ull swN = 0ull, bmN0 = 0ull, bmN1 = 0ull, bmN2 = 0ull;
        if (tid < 64) {
            int rr2 = rbase + 64 + tid;
            if (w + 1 < nwords && rr2 < M) {
                swN = g_maskT[(size_t)(w + 1) * NBOX + rr2];
                const ull* bp = g_nzw[rr2];
                bmN0 = bp[0]; bmN1 = bp[1]; bmN2 = bp[2];
            }
        }

        // phase A: speculatively load up to 4 future-word mask values for my row
        int nwl = 0; int wli[4]; ull wlv[4];
        ull b0 = bmR0, b1 = bmR1, b2 = bmR2;
        if (tid < cnt) {
            while (nwl < 4) {
                int i;
                if      (b0) { i = __ffsll((long long)b0) - 1;       b0 &= b0 - 1; }
                else if (b1) { i = __ffsll((long long)b1) - 1 + 64;  b1 &= b1 - 1; }
                else if (b2) { i = __ffsll((long long)b2) - 1 + 128; b2 &= b2 - 1; }
                else break;
                wli[nwl] = i;
                wlv[nwl] = g_maskT[(size_t)i * NBOX + rbase + tid];
                nwl++;
            }
        }
        if (tid < 64) selfw[tid] = swR;
        if (wrp == 0) {
            unsigned bl = __ballot_sync(0xffffffffu, swR != 0ull);
            if (lane == 0) act_lo = bl;
        } else if (wrp == 1) {
            unsigned bl = __ballot_sync(0xffffffffu, swR != 0ull);
            if (lane == 0) act_hi = bl;
        }
        __syncthreads();

        // phase B: sparse closure (thread 0); sup seeded straight from smem remv
        if (tid == 0) {
            ull sup = remv[w];
            const ull active = ((ull)act_hi << 32) | act_lo;
            const ull full = (cnt < 64) ? ((1ull << cnt) - 1ull) : ~0ull;
            ull act = active & ~sup & full;
            while (act) {
                int rr = __ffsll((long long)act) - 1;
                sup |= selfw[rr];
                ull above = (rr >= 63) ? 0ull : (~0ull << (rr + 1));
                act = active & ~sup & above;
            }
            kb_s = ~sup & full;
        }
        __syncthreads();

        // phase C: kept rows propagate their sparse suppression into remv
        const ull kb = kb_s;
        if (tid < cnt && ((kb >> tid) & 1ull)) {
            g_keep[g_sidx[rbase + tid]] = 1;
            #pragma unroll
            for (int q = 0; q < 4; q++)
                if (q < nwl) atomicOr(&remv[wli[q]], wlv[q]);
            // rare leftover bits beyond the 4 speculated
            while (b0) { int i = __ffsll((long long)b0) - 1;       b0 &= b0 - 1;
                         atomicOr(&remv[i], g_maskT[(size_t)i * NBOX + rbase + tid]); }
            while (b1) { int i = __ffsll((long long)b1) - 1 + 64;  b1 &= b1 - 1;
                         atomicOr(&remv[i], g_maskT[(size_t)i * NBOX + rbase + tid]); }
            while (b2) { int i = __ffsll((long long)b2) - 1 + 128; b2 &= b2 - 1;
                         atomicOr(&remv[i], g_maskT[(size_t)i * NBOX + rbase + tid]); }
        }
        swR = swN; bmR0 = bmN0; bmR1 = bmN1; bmR2 = bmN2;
        __syncthreads();
    }

    // ---- output tail: 256 threads write all 9216 rows ----
    for (int n = tid; n < NBOX; n += 256) {
        float m = g_keep[n] ? 1.0f : 0.0f;
        float4 bx = g_boxes[n];
        float s = g_scores[n];
        float* o = out + (size_t)n * 5;
        o[0] = bx.x * m; o[1] = bx.y * m; o[2] = bx.z * m; o[3] = bx.w * m; o[4] = s * m;
    }
}

// ---------------- launch ----------------
extern "C" void kernel_launch(void* const* d_in, const int* in_sizes, int n_in,
                              void* d_out, int out_size)
{
    const float* fm = (const float*)d_in[0];
    const float* w1 = (const float*)d_in[1];
    const float* b1 = (const float*)d_in[2];
    const float* w2 = (const float*)d_in[3];
    const float* b2 = (const float*)d_in[4];
    const float* w3 = (const float*)d_in[5];
    const float* b3 = (const float*)d_in[6];

    k_conv    <<<dim3(16, 16), 128>>>(fm, w1, b1);
    k_heads   <<<256, 128>>>(w2, b2, w3, b3);
    k_rankmask<<<NBLK, 256>>>();
    k_scanout <<<1, 256>>>((float*)d_out);
}